// round 8
// baseline (speedup 1.0000x reference)
#include <cuda_runtime.h>
#include <cuda_fp16.h>
#include <cstdint>

// ---------------- problem constants ----------------
#define D_DIM   256      // embedding dim = GEMM K
#define NHID    512      // H*K_hid = GEMM N
#define TM      128      // nodes per CTA = GEMM M
#define T1      256      // threads in score kernel (8 warps)
#define N_MAX   200704

// g_B4: W1 transposed, fp16, mma-fragment packed with CONTIGUOUS-k permutation.
// uint4 index q = ht*1024 + ks*64 + p*32 + l   (ht=0..15 tiles of 32 n-cols,
// ks=0..15 k16-steps, p=0..1 j-pairs, l=lane; g=l>>2, t=l&3).
// kb = ks*16 + 4t;  n0 = ht*32 + p*16 + g;  n1 = n0 + 8;  B[n][k] = W1[n>>7][k][n&127].
__device__ __align__(16) uint4 g_B4[NHID * D_DIM / 8];   // 8192 uint4 = 128KB
__device__ __align__(16) float g_escore[N_MAX * 4];      // e = exp(score) per node/head

// smem layout (bytes): b1 | w2 | B triple buffer (3 x 16KB)
#define SMB_B1   0
#define SMB_W2   2048
#define SMB_BUF  4096
#define SMB_TOT  53248     // 52KB -> 2 CTAs/SM

__device__ __forceinline__ uint32_t h2pack(float a, float b) {
    __half2 h = __floats2half2_rn(a, b);
    return *(uint32_t*)&h;
}

__device__ __forceinline__ uint32_t smem_u32(const void* p) {
    uint32_t r;
    asm("{ .reg .u64 t; cvta.to.shared.u64 t, %1; cvt.u32.u64 %0, t; }" : "=r"(r) : "l"(p));
    return r;
}

__device__ __forceinline__ void cp16(uint32_t dst, const void* src) {
    asm volatile("cp.async.cg.shared.global [%0], [%1], 16;" :: "r"(dst), "l"(src));
}

#define MMA_F16(cj, av, bx, by) \
    asm volatile( \
        "mma.sync.aligned.m16n8k16.row.col.f32.f16.f16.f32 " \
        "{%0,%1,%2,%3}, {%4,%5,%6,%7}, {%8,%9}, {%0,%1,%2,%3};" \
        : "+f"((cj)[0]), "+f"((cj)[1]), "+f"((cj)[2]), "+f"((cj)[3]) \
        : "r"((av).x), "r"((av).y), "r"((av).z), "r"((av).w), "r"(bx), "r"(by))

// ---------------- kernel 0: pack W1 -> fp16 fragment layout ----------------
__global__ void mhap_prep_kernel(const float* __restrict__ W1) {
    int q = blockIdx.x * blockDim.x + threadIdx.x;    // 8192 total
    if (q >= NHID * D_DIM / 8) return;
    int l  = q & 31;
    int p  = (q >> 5) & 1;
    int ks = (q >> 6) & 15;
    int ht = q >> 10;
    int g = l >> 2, t = l & 3;
    int n0 = ht * 32 + p * 16 + g;
    int n1 = n0 + 8;
    int kb = ks * 16 + 4 * t;
    #define B_EL(n, k) W1[((n) >> 7) * (D_DIM * 128) + (k) * 128 + ((n) & 127)]
    uint4 o;
    o.x = h2pack(B_EL(n0, kb),     B_EL(n0, kb + 1));
    o.y = h2pack(B_EL(n0, kb + 2), B_EL(n0, kb + 3));
    o.z = h2pack(B_EL(n1, kb),     B_EL(n1, kb + 1));
    o.w = h2pack(B_EL(n1, kb + 2), B_EL(n1, kb + 3));
    #undef B_EL
    g_B4[q] = o;
}

// ---------------- kernel 1: e-scores via mma.sync fp16; A in registers ----------------
__global__ void __launch_bounds__(T1, 2) mhap_score_kernel(
    const float* __restrict__ x,
    const float* __restrict__ b1g,
    const float* __restrict__ w2g,
    const float* __restrict__ b2g,
    int N)
{
    extern __shared__ float sm[];
    char* smc = (char*)sm;
    const int tid = threadIdx.x;
    const int w   = tid >> 5;
    const int l   = tid & 31;
    const int g   = l >> 2;
    const int t   = l & 3;
    const long node0 = (long)blockIdx.x * TM;
    const uint32_t smb = smem_u32(sm);

    // prefetch B tiles 0 and 1 (16 KB each) into buffers 0,1 of 3
    {
        uint32_t d0 = smb + SMB_BUF;
        #pragma unroll
        for (int e = 0; e < 4; ++e) {
            int qb = e * 256 + tid;
            cp16(d0 + (uint32_t)qb * 16u, g_B4 + qb);
        }
        asm volatile("cp.async.commit_group;" ::: "memory");
        #pragma unroll
        for (int e = 0; e < 4; ++e) {
            int qb = e * 256 + tid;
            cp16(d0 + 16384u + (uint32_t)qb * 16u, g_B4 + 1024 + qb);
        }
        asm volatile("cp.async.commit_group;" ::: "memory");
    }

    // biases / W2 into smem
    for (int i = tid; i < NHID; i += T1) {
        ((float*)(smc + SMB_B1))[i] = b1g[i];
        ((float*)(smc + SMB_W2))[i] = w2g[i];
    }

    // A fragments straight into registers (k-permuted so each read is one float4)
    const long r0 = node0 + w * 16 + g;
    const long r1 = r0 + 8;
    const bool v0 = r0 < N, v1 = r1 < N;
    uint4 areg[16];
    #pragma unroll
    for (int ks = 0; ks < 16; ++ks) {
        int kb = ks * 16 + 4 * t;
        float4 f0 = make_float4(0.f, 0.f, 0.f, 0.f), f1 = f0;
        if (v0) f0 = *(const float4*)(x + r0 * D_DIM + kb);
        if (v1) f1 = *(const float4*)(x + r1 * D_DIM + kb);
        areg[ks].x = h2pack(f0.x, f0.y);
        areg[ks].y = h2pack(f1.x, f1.y);
        areg[ks].z = h2pack(f0.z, f0.w);
        areg[ks].w = h2pack(f1.z, f1.w);
    }

    float s00 = 0.f, s01 = 0.f, s02 = 0.f, s03 = 0.f;   // row g,   heads 0..3
    float s10 = 0.f, s11 = 0.f, s12 = 0.f, s13 = 0.f;   // row g+8
    const float* s_b1 = (const float*)(smc + SMB_B1);
    const float* s_w2 = (const float*)(smc + SMB_W2);

    for (int ht = 0; ht < 16; ++ht) {
        if (ht < 15) asm volatile("cp.async.wait_group 1;" ::: "memory");
        else         asm volatile("cp.async.wait_group 0;" ::: "memory");
        __syncthreads();   // single barrier per tile: tile ht fully arrived

        // prefetch tile ht+2 into buffer (ht+2)%3 (safe: nobody reads it this iter)
        int nxt = ht + 2;
        if (nxt < 16) {
            const uint4* src = g_B4 + nxt * 1024;
            uint32_t dstb = smb + SMB_BUF + (uint32_t)(nxt % 3) * 16384u;
            #pragma unroll
            for (int e = 0; e < 4; ++e) {
                int qb = e * 256 + tid;
                cp16(dstb + (uint32_t)qb * 16u, src + qb);
            }
            asm volatile("cp.async.commit_group;" ::: "memory");
        }

        const uint4* Bu = (const uint4*)(smc + SMB_BUF) + (ht % 3) * 1024 + l;

        float c[4][4];
        #pragma unroll
        for (int j = 0; j < 4; ++j)
            c[j][0] = c[j][1] = c[j][2] = c[j][3] = 0.f;

        #pragma unroll
        for (int ks = 0; ks < 16; ++ks) {
            uint4 bA = Bu[ks * 64];
            uint4 bB = Bu[ks * 64 + 32];
            MMA_F16(c[0], areg[ks], bA.x, bA.y);
            MMA_F16(c[1], areg[ks], bA.z, bA.w);
            MMA_F16(c[2], areg[ks], bB.x, bB.y);
            MMA_F16(c[3], areg[ks], bB.z, bB.w);
        }

        // epilogue: relu + W2 dot for this tile's 32 hidden cols (head = ht>>2)
        float p0 = 0.f, p1 = 0.f;
        int nb = ht * 32 + 2 * t;
        #pragma unroll
        for (int j = 0; j < 4; ++j) {
            int n = nb + j * 8;
            float w2a = s_w2[n], w2b = s_w2[n + 1];
            float ba  = s_b1[n], bb = s_b1[n + 1];
            p0 += fmaxf(c[j][0] + ba, 0.f) * w2a + fmaxf(c[j][1] + bb, 0.f) * w2b;
            p1 += fmaxf(c[j][2] + ba, 0.f) * w2a + fmaxf(c[j][3] + bb, 0.f) * w2b;
        }
        switch (ht >> 2) {
            case 0: s00 += p0; s10 += p1; break;
            case 1: s01 += p0; s11 += p1; break;
            case 2: s02 += p0; s12 += p1; break;
            default: s03 += p0; s13 += p1; break;
        }
    }

    #pragma unroll
    for (int off = 1; off <= 2; off <<= 1) {
        s00 += __shfl_xor_sync(0xFFFFFFFFu, s00, off);
        s01 += __shfl_xor_sync(0xFFFFFFFFu, s01, off);
        s02 += __shfl_xor_sync(0xFFFFFFFFu, s02, off);
        s03 += __shfl_xor_sync(0xFFFFFFFFu, s03, off);
        s10 += __shfl_xor_sync(0xFFFFFFFFu, s10, off);
        s11 += __shfl_xor_sync(0xFFFFFFFFu, s11, off);
        s12 += __shfl_xor_sync(0xFFFFFFFFu, s12, off);
        s13 += __shfl_xor_sync(0xFFFFFFFFu, s13, off);
    }
    if (t == 0) {
        // store e = exp(score) directly (softmax without max-shift: |score| << 80)
        float b20 = b2g[0], b21 = b2g[1], b22 = b2g[2], b23 = b2g[3];
        if (r0 < N) {
            float4 o;
            o.x = __expf(s00 + b20); o.y = __expf(s01 + b21);
            o.z = __expf(s02 + b22); o.w = __expf(s03 + b23);
            *(float4*)(g_escore + r0 * 4) = o;
        }
        if (r1 < N) {
            float4 o;
            o.x = __expf(s10 + b20); o.y = __expf(s11 + b21);
            o.z = __expf(s12 + b22); o.w = __expf(s13 + b23);
            *(float4*)(g_escore + r1 * 4) = o;
        }
    }
}

// ---------------- kernel 2: segment normalize + weighted segment-sum ----------------
// grid = (G, 2): blockIdx.y selects which 128-dim half this CTA owns.
__device__ __forceinline__ int lower_bound_i(const int* __restrict__ a, int n, int v) {
    int lo = 0, hi = n;
    while (lo < hi) { int mid = (lo + hi) >> 1; if (a[mid] < v) lo = mid + 1; else hi = mid; }
    return lo;
}

__global__ void __launch_bounds__(256) mhap_pool_kernel(
    const float* __restrict__ x, const int* __restrict__ seg,
    float* __restrict__ out, int N)
{
    const int g = blockIdx.x;
    const int half = blockIdx.y;
    const int tid = threadIdx.x;
    const int wid = tid >> 5, lid = tid & 31;
    __shared__ float s_red[8][4];
    __shared__ float s_inv[4];
    __shared__ float s_w[256];
    __shared__ float4 s_acc[256];
    __shared__ int s_bounds[2];

    if (tid == 0) s_bounds[0] = lower_bound_i(seg, N, g);
    if (tid == 32) s_bounds[1] = lower_bound_i(seg, N, g + 1);
    __syncthreads();
    const int lo = s_bounds[0], hi = s_bounds[1];

    const int d4 = half * 128 + (tid & 31) * 4;   // this thread's 4 dims
    const int rg = tid >> 5;                      // row-group 0..7

    if (lo >= hi) {                               // empty segment -> zeros
        if (tid < 32) {
            float4 z = make_float4(0.f, 0.f, 0.f, 0.f);
            *(float4*)(out + (long)g * D_DIM + half * 128 + tid * 4) = z;
        }
        return;
    }

    // ---- pass 1: per-head sum of e ----
    float t0 = 0.f, t1 = 0.f, t2 = 0.f, t3 = 0.f;
    for (int n = lo + tid; n < hi; n += 256) {
        float4 ev = *(const float4*)(g_escore + (long)n * 4);
        t0 += ev.x; t1 += ev.y; t2 += ev.z; t3 += ev.w;
    }
    #pragma unroll
    for (int off = 16; off; off >>= 1) {
        t0 += __shfl_xor_sync(0xFFFFFFFFu, t0, off);
        t1 += __shfl_xor_sync(0xFFFFFFFFu, t1, off);
        t2 += __shfl_xor_sync(0xFFFFFFFFu, t2, off);
        t3 += __shfl_xor_sync(0xFFFFFFFFu, t3, off);
    }
    if (lid == 0) { s_red[wid][0] = t0; s_red[wid][1] = t1; s_red[wid][2] = t2; s_red[wid][3] = t3; }
    __syncthreads();
    if (tid == 0) {
        float a0 = 0.f, a1 = 0.f, a2 = 0.f, a3 = 0.f;
        for (int ww = 0; ww < 8; ++ww) {
            a0 += s_red[ww][0]; a1 += s_red[ww][1]; a2 += s_red[ww][2]; a3 += s_red[ww][3];
        }
        s_inv[0] = 0.25f / a0; s_inv[1] = 0.25f / a1;
        s_inv[2] = 0.25f / a2; s_inv[3] = 0.25f / a3;
    }
    __syncthreads();
    const float i0 = s_inv[0], i1 = s_inv[1], i2 = s_inv[2], i3 = s_inv[3];

    // ---- pass 2: weighted sum; 8 row-groups x 32 dim-lanes; 4 indep accumulators ----
    float4 a0 = make_float4(0.f, 0.f, 0.f, 0.f), a1 = a0, a2 = a0, a3 = a0;

    for (int base = lo; base < hi; base += 256) {
        int cnt = min(256, hi - base);
        __syncthreads();
        if (tid < cnt) {
            float4 ev = *(const float4*)(g_escore + (long)(base + tid) * 4);
            s_w[tid] = ev.x * i0 + ev.y * i1 + ev.z * i2 + ev.w * i3;
        }
        __syncthreads();
        const float* xb = x + (long)base * D_DIM + d4;
        int j = rg;
        for (; j + 24 < cnt; j += 32) {
            float w0 = s_w[j], w1 = s_w[j + 8], w2 = s_w[j + 16], w3 = s_w[j + 24];
            float4 x0 = *(const float4*)(xb + (long)j * D_DIM);
            float4 x1 = *(const float4*)(xb + (long)(j + 8) * D_DIM);
            float4 x2 = *(const float4*)(xb + (long)(j + 16) * D_DIM);
            float4 x3 = *(const float4*)(xb + (long)(j + 24) * D_DIM);
            a0.x = fmaf(w0, x0.x, a0.x); a0.y = fmaf(w0, x0.y, a0.y);
            a0.z = fmaf(w0, x0.z, a0.z); a0.w = fmaf(w0, x0.w, a0.w);
            a1.x = fmaf(w1, x1.x, a1.x); a1.y = fmaf(w1, x1.y, a1.y);
            a1.z = fmaf(w1, x1.z, a1.z); a1.w = fmaf(w1, x1.w, a1.w);
            a2.x = fmaf(w2, x2.x, a2.x); a2.y = fmaf(w2, x2.y, a2.y);
            a2.z = fmaf(w2, x2.z, a2.z); a2.w = fmaf(w2, x2.w, a2.w);
            a3.x = fmaf(w3, x3.x, a3.x); a3.y = fmaf(w3, x3.y, a3.y);
            a3.z = fmaf(w3, x3.z, a3.z); a3.w = fmaf(w3, x3.w, a3.w);
        }
        for (; j < cnt; j += 8) {
            float wv = s_w[j];
            float4 xv = *(const float4*)(xb + (long)j * D_DIM);
            a0.x = fmaf(wv, xv.x, a0.x); a0.y = fmaf(wv, xv.y, a0.y);
            a0.z = fmaf(wv, xv.z, a0.z); a0.w = fmaf(wv, xv.w, a0.w);
        }
    }

    a0.x = (a0.x + a1.x) + (a2.x + a3.x);
    a0.y = (a0.y + a1.y) + (a2.y + a3.y);
    a0.z = (a0.z + a1.z) + (a2.z + a3.z);
    a0.w = (a0.w + a1.w) + (a2.w + a3.w);
    s_acc[tid] = a0;
    __syncthreads();

    // reduce across 8 row-groups, write coalesced float4
    if (tid < 32) {
        float4 o = s_acc[tid];
        #pragma unroll
        for (int k = 1; k < 8; ++k) {
            float4 r = s_acc[tid + 32 * k];
            o.x += r.x; o.y += r.y; o.z += r.z; o.w += r.w;
        }
        *(float4*)(out + (long)g * D_DIM + half * 128 + tid * 4) = o;
    }
}

// ---------------- launch ----------------
extern "C" void kernel_launch(void* const* d_in, const int* in_sizes, int n_in,
                              void* d_out, int out_size) {
    const float* x   = (const float*)d_in[0];
    const int*   seg = (const int*)d_in[1];
    int base = 2;
    if (n_in >= 7 && in_sizes[2] == 1) base = 3;   // skip num_graphs scalar if present
    const float* W1 = (const float*)d_in[base];
    const float* b1 = (const float*)d_in[base + 1];
    const float* W2 = (const float*)d_in[base + 2];
    const float* b2 = (const float*)d_in[base + 3];

    const int N = in_sizes[1];
    const int G = out_size / D_DIM;

    mhap_prep_kernel<<<(NHID * D_DIM / 8 + 255) / 256, 256>>>(W1);

    cudaFuncSetAttribute(mhap_score_kernel,
                         cudaFuncAttributeMaxDynamicSharedMemorySize, SMB_TOT);
    mhap_score_kernel<<<(N + TM - 1) / TM, T1, SMB_TOT>>>(x, b1, W2, b2, N);

    dim3 pg(G, 2);
    mhap_pool_kernel<<<pg, 256>>>(x, seg, (float*)d_out, N);
}